// round 1
// baseline (speedup 1.0000x reference)
#include <cuda_runtime.h>
#include <cuda_bf16.h>

// BERTEmbedding: out[b,l,:] = token_table[seq[b,l],:] 
//                           + mean_{g<cnt}(genre_table[gids[seq[b,l],g],:])
//                           + pos_table[l,:]
//
// B=256, L=200, EMBED=128 (32 float4), MAX_G=8.
// One warp per (b,l) token; lane k owns float4 at dim 4k.

#define NUM_TOKENS (256 * 200)
#define SEQ_L 200
#define MAX_G 8

__global__ __launch_bounds__(256) void bert_embed_kernel(
    const int* __restrict__ seq,          // [256,200]
    const float4* __restrict__ tok_tab,   // [VOCAB,32]
    const float4* __restrict__ gen_tab,   // [21,32]
    const float4* __restrict__ pos_tab,   // [200,32]
    const int* __restrict__ tgid,         // [VOCAB,8]
    const int* __restrict__ gcnt,         // [VOCAB]
    float4* __restrict__ out)             // [256*200,32]
{
    const int warp = (blockIdx.x * blockDim.x + threadIdx.x) >> 5;
    const int lane = threadIdx.x & 31;
    if (warp >= NUM_TOKENS) return;

    const int l = warp % SEQ_L;
    const int t = __ldg(&seq[warp]);          // warp-uniform broadcast
    const int cnt = __ldg(&gcnt[t]);          // warp-uniform broadcast

    // Issue the two big independent loads up front for MLP.
    float4 acc = __ldg(&tok_tab[t * 32 + lane]);
    float4 pos = __ldg(&pos_tab[l * 32 + lane]);

    float4 gsum = make_float4(0.f, 0.f, 0.f, 0.f);
    #pragma unroll
    for (int g = 0; g < MAX_G; g++) {
        if (g < cnt) {
            const int gid = __ldg(&tgid[t * MAX_G + g]);   // warp-uniform
            const float4 ge = __ldg(&gen_tab[gid * 32 + lane]); // L1-hot (10.5KB table)
            gsum.x += ge.x; gsum.y += ge.y; gsum.z += ge.z; gsum.w += ge.w;
        }
    }

    const float inv = 1.0f / (float)cnt;
    acc.x += pos.x + gsum.x * inv;
    acc.y += pos.y + gsum.y * inv;
    acc.z += pos.z + gsum.z * inv;
    acc.w += pos.w + gsum.w * inv;

    out[warp * 32 + lane] = acc;
}

extern "C" void kernel_launch(void* const* d_in, const int* in_sizes, int n_in,
                              void* d_out, int out_size) {
    const int*    seq     = (const int*)d_in[0];
    const float4* tok_tab = (const float4*)d_in[1];
    const float4* gen_tab = (const float4*)d_in[2];
    const float4* pos_tab = (const float4*)d_in[3];
    const int*    tgid    = (const int*)d_in[4];
    const int*    gcnt    = (const int*)d_in[5];
    float4*       out     = (float4*)d_out;

    // one warp per token, 8 warps (256 threads) per block
    const int blocks = (NUM_TOKENS * 32 + 255) / 256;  // 6400
    bert_embed_kernel<<<blocks, 256>>>(seq, tok_tab, gen_tab, pos_tab, tgid, gcnt, out);
}